// round 6
// baseline (speedup 1.0000x reference)
#include <cuda_runtime.h>
#include <cuda_bf16.h>

#define NPATCH   8192
#define P        41
#define PPB      2            // patches per block
#define TPP      48           // threads per patch (41 active columns)
// float2 accumulator: acc[b in 0..3][si in 0..9][c in 0..47]
//   .x accumulates wy*c0v (slot s = si+3), .y accumulates wy*c1v (slot s+1)
#define SLOTS2   10
#define SSTRIDE  48                      // float2 per slot row
#define BSTRIDE2 (SLOTS2 * SSTRIDE)     // 480 float2 per y-bin
#define PSTRIDE2 (4 * BSTRIDE2)         // 1920 float2 per patch

// ---------------------------------------------------------------------------
// Fused kernel: gradients + orientation binning + separable spatial pooling
// + full normalization chain. One block = 2 patches, 96 threads.
// ---------------------------------------------------------------------------
__global__ __launch_bounds__(PPB * TPP, 7)
void sift_fused_kernel(const float* __restrict__ x,
                       float* __restrict__ out)
{
    __shared__ float2 cs2[PPB * PSTRIDE2];
    __shared__ float  sdesc[PPB][128];

    const int tid  = threadIdx.x;
    const int lane = tid & 31;

    // zero accumulators (STS.64)
    #pragma unroll 8
    for (int k = tid; k < PPB * PSTRIDE2; k += PPB * TPP)
        cs2[k] = make_float2(0.0f, 0.0f);
    __syncthreads();

    const int pl = tid / TPP;        // patch-in-block
    const int c  = tid % TPP;        // column id (active if < 41)
    const int gp = blockIdx.x * PPB + pl;

    if (c < P) {
        const float* xp = x + (size_t)gp * (P * P);
        const int cm1 = (c > 0)     ? c - 1 : 0;
        const int cp1 = (c < P - 1) ? c + 1 : P - 1;
        const float* pm = xp + cm1;
        const float* pc = xp + c;
        const float* pp = xp + cp1;

        // column gaussian factor: exp(-(c-20)^2/1681)
        const float fc = (float)(c - 20);
        const float colf = exp2f(fc * fc * (-1.44269504f / 1681.0f));

        float2* pbase = cs2 + pl * PSTRIDE2 + c;   // (b,si): pbase[b*BSTRIDE2 + si*SSTRIDE]

        // rolling 3x3 window (only the 7 values actually needed)
        float cur_m1 = __ldg(pm);
        float cur_c  = __ldg(pc);
        float cur_p1 = __ldg(pp);
        float prev_c = cur_c;              // replicate-pad top edge

        #pragma unroll
        for (int y = 0; y < P; ++y) {
            const int yn = (y < P - 1) ? (y + 1) : (P - 1);   // replicate bottom
            const float nxt_m1 = __ldg(pm + yn * P);
            const float nxt_c  = __ldg(pc + yn * P);
            const float nxt_p1 = __ldg(pp + yn * P);

            const float gxv = cur_p1 - cur_m1;
            const float gyv = nxt_c  - prev_c;

            // gaussian weight: row factor has a compile-time-constant exp2 arg
            const float rowf = exp2f((float)((y - 20) * (y - 20)) *
                                     (-1.44269504f / 1681.0f));
            const float gw = colf * rowf;

            // weighted magnitude: sqrt(gx^2+gy^2+1e-10) * gw
            const float m2  = fmaf(gyv, gyv, fmaf(gxv, gxv, 1e-10f));
            const float mag = m2 * rsqrtf(m2) * gw;

            // angle -> o = atan2(gy, gx+1e-10)*(4/pi) + 8, o in [4, 12]
            const float gxe = gxv + 1e-10f;
            const float ax = fabsf(gxe), ay = fabsf(gyv);
            const float mn = fminf(ax, ay);
            const float mx = fmaxf(fmaxf(ax, ay), 1e-30f);
            const float q  = __fdividef(mn, mx);          // MUFU.RCP + FMUL
            const float s  = q * q;
            // minimax atan(q)*(4/pi) on [0,1], max err ~3e-6
            const float rb = q * fmaf(s, fmaf(s, fmaf(s, fmaf(s,
                                fmaf(s, -0.01492388f, 0.06704029f),
                                -0.14824694f), 0.24642712f), -0.42350938f),
                                1.27321060f);
            const float t1 = (ay > ax)    ? (2.0f - rb) : rb;
            const float t2 = (gxe < 0.0f) ? (4.0f - t1) : t1;
            const float o  = 8.0f + copysignf(t2, gyv);

            const int   i   = __float2int_rd(o);          // floor, in [3,12]
            const float wo1 = o - (float)i;
            const float c1v = wo1 * mag;                  // -> slot i+1
            const float c0v = mag - c1v;                  // -> slot i

            float2* ap = pbase + (i - 3) * SSTRIDE;

            // y pooling: triangular weights, compile-time constants per y.
            // one LDS.64 + 2 FFMA + one STS.64 per active bin.
            #pragma unroll
            for (int b = 0; b < 4; ++b) {
                const int u = y + 4 - 10 * b;
                if (u >= 0 && u <= 15) {
                    const float wy = 8.0f - fabsf((float)u - 7.5f);
                    float2 v = ap[b * BSTRIDE2];
                    v.x = fmaf(wy, c0v, v.x);
                    v.y = fmaf(wy, c1v, v.y);
                    ap[b * BSTRIDE2] = v;
                }
            }

            prev_c = cur_c;
            cur_m1 = nxt_m1; cur_c = nxt_c; cur_p1 = nxt_p1;
        }
    }
    __syncthreads();

    // x-fold reduction into sdesc.
    // unwrapped slot value: val(s) = X[s] + Y[s-1]; angular fold: s%8 == a,
    // s in [3,13]. X[s] = cs2[.., s-3, ..].x, Y[s-1] = cs2[.., s-4, ..].y.
    #pragma unroll
    for (int r = 0; r < 3; ++r) {
        const int o = c + r * TPP;
        if (o < 128) {
            const int a  = o >> 4;
            const int yb = (o >> 2) & 3;
            const int xb = o & 3;
            const int sA = (a >= 3) ? a : a + 8;     // in [3,10]
            const bool hasB = (a >= 3 && a <= 5);    // sB = a+8 in [11,13]
            const int sB = a + 8;
            const int cstart = 10 * xb - 4;
            const float2* row = cs2 + pl * PSTRIDE2 + yb * BSTRIDE2;
            float sum = 0.0f;
            #pragma unroll
            for (int dc = 0; dc < 16; ++dc) {
                const int cc = cstart + dc;
                if (cc >= 0 && cc < P) {
                    const float wx = 8.0f - fabsf((float)dc - 7.5f);
                    float v = row[(sA - 3) * SSTRIDE + cc].x;
                    if (sA >= 4) v += row[(sA - 4) * SSTRIDE + cc].y;
                    if (hasB) {
                        if (sB <= 12) v += row[(sB - 3) * SSTRIDE + cc].x;
                        v += row[(sB - 4) * SSTRIDE + cc].y;
                    }
                    sum = fmaf(wx, v, sum);
                }
            }
            sdesc[pl][o] = sum * 0.015625f;   // 1/64
        }
    }
    __syncthreads();

    // ---- fused normalization: warp 0 -> patch 0, warp 2 -> patch 1 ----
    // L2-normalize -> clip 0.2 -> L2-normalize -> L1-normalize -> sqrt(+1e-10)
    const int warp = tid >> 5;
    if ((warp & 1) == 0) {
        const int pw = warp >> 1;
        const float* sd = sdesc[pw];

        float v0 = sd[lane];
        float v1 = sd[lane + 32];
        float v2 = sd[lane + 64];
        float v3 = sd[lane + 96];

        float ss = v0 * v0 + v1 * v1 + v2 * v2 + v3 * v3;
        #pragma unroll
        for (int k = 16; k; k >>= 1) ss += __shfl_xor_sync(0xffffffffu, ss, k);
        float inv = 1.0f / fmaxf(sqrtf(ss), 1e-12f);
        v0 *= inv; v1 *= inv; v2 *= inv; v3 *= inv;

        v0 = fminf(fmaxf(v0, 0.0f), 0.2f);
        v1 = fminf(fmaxf(v1, 0.0f), 0.2f);
        v2 = fminf(fmaxf(v2, 0.0f), 0.2f);
        v3 = fminf(fmaxf(v3, 0.0f), 0.2f);

        float ss2 = v0 * v0 + v1 * v1 + v2 * v2 + v3 * v3;
        #pragma unroll
        for (int k = 16; k; k >>= 1) ss2 += __shfl_xor_sync(0xffffffffu, ss2, k);
        float inv2 = 1.0f / fmaxf(sqrtf(ss2), 1e-12f);
        v0 *= inv2; v1 *= inv2; v2 *= inv2; v3 *= inv2;

        float l1 = fabsf(v0) + fabsf(v1) + fabsf(v2) + fabsf(v3);
        #pragma unroll
        for (int k = 16; k; k >>= 1) l1 += __shfl_xor_sync(0xffffffffu, l1, k);
        float inv3 = 1.0f / fmaxf(l1, 1e-12f);

        float* d = out + (size_t)(blockIdx.x * PPB + pw) * 128;
        d[lane]      = sqrtf(fmaf(v0, inv3, 1e-10f));
        d[lane + 32] = sqrtf(fmaf(v1, inv3, 1e-10f));
        d[lane + 64] = sqrtf(fmaf(v2, inv3, 1e-10f));
        d[lane + 96] = sqrtf(fmaf(v3, inv3, 1e-10f));
    }
}

// ---------------------------------------------------------------------------
extern "C" void kernel_launch(void* const* d_in, const int* in_sizes, int n_in,
                              void* d_out, int out_size)
{
    const float* x = nullptr;
    for (int i = 0; i < n_in; ++i)
        if (in_sizes[i] == NPATCH * P * P) x = (const float*)d_in[i];
    // gk & pk inputs unused: gaussian is separable (recomputed analytically),
    // pooling weights are exact dyadic rationals baked in as constants.
    float* out = (float*)d_out;

    sift_fused_kernel<<<NPATCH / PPB, PPB * TPP>>>(x, out);
}

// round 7
// speedup vs baseline: 1.5139x; 1.5139x over previous
#include <cuda_runtime.h>
#include <cuda_bf16.h>

#define NPATCH   8192
#define P        41
#define PPB      2            // patches per block
#define TPP      48           // threads per patch (41 active columns)
#define NSLOT    11           // angular slots for floor(o) in [3,13]
#define CPAD     64           // slot stride ≡ 0 mod 32 banks → bank = column only
#define BSTRIDE  (NSLOT * CPAD)         // 704 floats per y-bin
#define PSTRIDE  (4 * BSTRIDE + 16)     // 2832: +16-float skew between patches

// exp(-d^2/1681) for d = 0..20 (matches reference gaussian to ~1e-7)
__device__ constexpr float GWH[21] = {
    1.00000000f, 0.99940530f, 0.99762329f, 0.99466037f, 0.99052702f,
    0.98523795f, 0.97881186f, 0.97127142f, 0.96264307f, 0.95295689f,
    0.94224646f, 0.93055415f, 0.91790324f, 0.90435309f, 0.88994353f,
    0.87472221f, 0.85873896f, 0.84204530f, 0.82469431f, 0.80674058f,
    0.78823926f
};

// ---------------------------------------------------------------------------
// Fused kernel: gradients + orientation binning + separable spatial pooling
// + full normalization chain. One block = 2 patches, 96 threads.
// ---------------------------------------------------------------------------
__global__ __launch_bounds__(PPB * TPP, 6)
void sift_fused_kernel(const float* __restrict__ x,
                       float* __restrict__ out)
{
    __shared__ float cs[PPB * PSTRIDE];
    __shared__ float sdesc[PPB][128];

    const int tid  = threadIdx.x;
    const int lane = tid & 31;

    // zero accumulators
    #pragma unroll 4
    for (int k = tid; k < PPB * PSTRIDE; k += PPB * TPP)
        cs[k] = 0.0f;
    __syncthreads();

    const int pl = tid / TPP;        // patch-in-block
    const int c  = tid % TPP;        // column id (active if < 41)
    const int gp = blockIdx.x * PPB + pl;

    if (c < P) {
        const float* xp = x + (size_t)gp * (P * P);
        const int cm1 = (c > 0)     ? c - 1 : 0;
        const int cp1 = (c < P - 1) ? c + 1 : P - 1;
        const float* pm = xp + cm1;
        const float* pc = xp + c;
        const float* pp = xp + cp1;

        // column gaussian factor: exp(-(c-20)^2/1681)
        const float fc = (float)(c - 20);
        const float colf = exp2f(fc * fc * (-1.44269504f / 1681.0f));

        float* pbase = cs + pl * PSTRIDE + c;   // (b,s): pbase[b*BSTRIDE + s*CPAD]

        // rolling 3x3 window (only the 7 values actually needed)
        float cur_m1 = __ldg(pm);
        float cur_c  = __ldg(pc);
        float cur_p1 = __ldg(pp);
        float prev_c = cur_c;              // replicate-pad top edge

        // per-pixel body: gy uses (nxt_c - prev_c); rowf is an immediate
        auto body = [&](int y, float nxt_c) {
            const float gxv = cur_p1 - cur_m1;
            const float gyv = nxt_c - prev_c;

            const float rowf = GWH[(y < 20) ? (20 - y) : (y - 20)];
            const float gw   = colf * rowf;

            // weighted magnitude: sqrt(gx^2+gy^2+1e-10) * gw
            const float m2  = fmaf(gyv, gyv, fmaf(gxv, gxv, 1e-10f));
            const float mag = m2 * rsqrtf(m2) * gw;

            // angle -> o = atan2(gy, gx+1e-10)*(4/pi) + 8, o in [4, 12]
            const float gxe = gxv + 1e-10f;
            const float ax = fabsf(gxe), ay = fabsf(gyv);
            const float mn = fminf(ax, ay);
            const float mx = fmaxf(fmaxf(ax, ay), 1e-30f);
            const float q  = __fdividef(mn, mx);          // MUFU.RCP + FMUL
            const float s  = q * q;
            // minimax atan(q)*(4/pi) on [0,1], max err ~3e-6
            const float rb = q * fmaf(s, fmaf(s, fmaf(s, fmaf(s,
                                fmaf(s, -0.01492388f, 0.06704029f),
                                -0.14824694f), 0.24642712f), -0.42350938f),
                                1.27321060f);
            const float t1 = (ay > ax)    ? (2.0f - rb) : rb;
            const float t2 = (gxe < 0.0f) ? (4.0f - t1) : t1;
            const float o  = 8.0f + copysignf(t2, gyv);

            const int   i   = __float2int_rd(o);          // floor, in [3,12]
            const float wo1 = o - (float)i;
            const float c1v = wo1 * mag;                  // -> slot i+1
            const float c0v = mag - c1v;                  // -> slot i

            float* ap = pbase + (i - 3) * CPAD;

            // y pooling: triangular weights, compile-time constants per y
            #pragma unroll
            for (int b = 0; b < 4; ++b) {
                const int u = y + 4 - 10 * b;
                if (u >= 0 && u <= 15) {
                    const float wy = 8.0f - fabsf((float)u - 7.5f);
                    ap[b * BSTRIDE]        += wy * c0v;
                    ap[b * BSTRIDE + CPAD] += wy * c1v;
                }
            }
        };

        #pragma unroll
        for (int y = 0; y < P - 1; ++y) {
            const float nxt_m1 = __ldg(pm + (y + 1) * P);
            const float nxt_c  = __ldg(pc + (y + 1) * P);
            const float nxt_p1 = __ldg(pp + (y + 1) * P);

            body(y, nxt_c);

            prev_c = cur_c;
            cur_m1 = nxt_m1; cur_c = nxt_c; cur_p1 = nxt_p1;
        }
        // peeled last row: replicate-pad bottom (nxt_c = cur_c), no loads
        body(P - 1, cur_c);
    }
    __syncthreads();

    // x-fold reduction into sdesc; angular fold: ang a <- slots {i%8==a}
    #pragma unroll
    for (int r = 0; r < 3; ++r) {
        const int o = c + r * TPP;
        if (o < 128) {
            const int a  = o >> 4;
            const int yb = (o >> 2) & 3;
            const int xb = o & 3;
            const int s1 = (a >= 3) ? (a - 3) : (a + 5);
            const int s2 = (a >= 3 && a <= 5) ? (a + 5) : -1;
            const int cstart = 10 * xb - 4;
            const float* row = cs + pl * PSTRIDE + yb * BSTRIDE;
            float sum = 0.0f;
            #pragma unroll
            for (int dc = 0; dc < 16; ++dc) {
                const int cc = cstart + dc;
                if (cc >= 0 && cc < P) {
                    const float wx = 8.0f - fabsf((float)dc - 7.5f);
                    float v = row[s1 * CPAD + cc];
                    if (s2 >= 0) v += row[s2 * CPAD + cc];
                    sum = fmaf(wx, v, sum);
                }
            }
            sdesc[pl][o] = sum * 0.015625f;   // 1/64
        }
    }
    __syncthreads();

    // ---- fused normalization: warp 0 -> patch 0, warp 2 -> patch 1 ----
    // L2-normalize -> clip 0.2 -> L2-normalize -> L1-normalize -> sqrt(+1e-10)
    const int warp = tid >> 5;
    if ((warp & 1) == 0) {
        const int pw = warp >> 1;
        const float* sd = sdesc[pw];

        float v0 = sd[lane];
        float v1 = sd[lane + 32];
        float v2 = sd[lane + 64];
        float v3 = sd[lane + 96];

        float ss = v0 * v0 + v1 * v1 + v2 * v2 + v3 * v3;
        #pragma unroll
        for (int k = 16; k; k >>= 1) ss += __shfl_xor_sync(0xffffffffu, ss, k);
        float inv = 1.0f / fmaxf(sqrtf(ss), 1e-12f);
        v0 *= inv; v1 *= inv; v2 *= inv; v3 *= inv;

        v0 = fminf(fmaxf(v0, 0.0f), 0.2f);
        v1 = fminf(fmaxf(v1, 0.0f), 0.2f);
        v2 = fminf(fmaxf(v2, 0.0f), 0.2f);
        v3 = fminf(fmaxf(v3, 0.0f), 0.2f);

        float ss2 = v0 * v0 + v1 * v1 + v2 * v2 + v3 * v3;
        #pragma unroll
        for (int k = 16; k; k >>= 1) ss2 += __shfl_xor_sync(0xffffffffu, ss2, k);
        float inv2 = 1.0f / fmaxf(sqrtf(ss2), 1e-12f);
        v0 *= inv2; v1 *= inv2; v2 *= inv2; v3 *= inv2;

        float l1 = fabsf(v0) + fabsf(v1) + fabsf(v2) + fabsf(v3);
        #pragma unroll
        for (int k = 16; k; k >>= 1) l1 += __shfl_xor_sync(0xffffffffu, l1, k);
        float inv3 = 1.0f / fmaxf(l1, 1e-12f);

        float* d = out + (size_t)(blockIdx.x * PPB + pw) * 128;
        d[lane]      = sqrtf(fmaf(v0, inv3, 1e-10f));
        d[lane + 32] = sqrtf(fmaf(v1, inv3, 1e-10f));
        d[lane + 64] = sqrtf(fmaf(v2, inv3, 1e-10f));
        d[lane + 96] = sqrtf(fmaf(v3, inv3, 1e-10f));
    }
}

// ---------------------------------------------------------------------------
extern "C" void kernel_launch(void* const* d_in, const int* in_sizes, int n_in,
                              void* d_out, int out_size)
{
    const float* x = nullptr;
    for (int i = 0; i < n_in; ++i)
        if (in_sizes[i] == NPATCH * P * P) x = (const float*)d_in[i];
    // gk & pk inputs unused: gaussian is separable (baked in as constants),
    // pooling weights are exact dyadic rationals baked in as constants.
    float* out = (float*)d_out;

    sift_fused_kernel<<<NPATCH / PPB, PPB * TPP>>>(x, out);
}